// round 1
// baseline (speedup 1.0000x reference)
#include <cuda_runtime.h>

// Problem constants
#define LY   6
#define NH   8
#define DM   512
#define FF   2048
#define BB   8
#define TT   512
#define SS   1024
#define DK   64
#define LAYER 5

// GEMM tiling
#define GBM 64
#define GBN 64
#define GBK 16

// ---------------- scratch (device globals; no allocation allowed) -------------
__device__ float g_n  [BB*TT*DM];       // LN output
__device__ float g_q  [BB*TT*DM];
__device__ float g_k  [BB*SS*DM];
__device__ float g_v  [BB*SS*DM];
__device__ float g_at [BB*TT*DM];       // attention output (pre O-proj)
__device__ float g_x  [BB*TT*DM];       // running residual
__device__ float g_ff [BB*TT*FF];       // FFN hidden
__device__ float g_sc [(size_t)BB*NH*TT*SS];  // attention scores/probs

// ---------------- LayerNorm: one block per row of 512 ------------------------
__global__ __launch_bounds__(128) void ln_kernel(
    const float* __restrict__ x, const float* __restrict__ g,
    const float* __restrict__ b, float* __restrict__ out)
{
    int row = blockIdx.x;
    const float* xr = x + (size_t)row * DM;
    float* orow = out + (size_t)row * DM;
    int tid = threadIdx.x;

    float vals[4];
    float s = 0.f, s2 = 0.f;
#pragma unroll
    for (int i = 0; i < 4; i++) {
        float v = xr[tid + i * 128];
        vals[i] = v; s += v; s2 += v * v;
    }
#pragma unroll
    for (int o = 16; o; o >>= 1) {
        s  += __shfl_down_sync(0xffffffffu, s,  o);
        s2 += __shfl_down_sync(0xffffffffu, s2, o);
    }
    __shared__ float rs[4], rs2[4];
    int wid = tid >> 5, lane = tid & 31;
    if (lane == 0) { rs[wid] = s; rs2[wid] = s2; }
    __syncthreads();
    if (tid == 0) {
        float a = 0.f, a2 = 0.f;
#pragma unroll
        for (int w = 0; w < 4; w++) { a += rs[w]; a2 += rs2[w]; }
        rs[0] = a; rs2[0] = a2;
    }
    __syncthreads();
    float mean = rs[0] * (1.0f / DM);
    float var  = rs2[0] * (1.0f / DM) - mean * mean;
    float inv  = rsqrtf(var + 1e-5f);
#pragma unroll
    for (int i = 0; i < 4; i++) {
        int c = tid + i * 128;
        orow[c] = (vals[i] - mean) * inv * g[c] + b[c];
    }
}

// ---------------- Generic tiled GEMM: C = epi(A[M,K] @ W[K,N] + bias) --------
// mode 0: +bias ; mode 1: relu(+bias) ; mode 2: +bias + res (res same shape as C)
__global__ __launch_bounds__(256) void gemm_proj(
    const float* __restrict__ A, const float* __restrict__ W,
    const float* __restrict__ bias, const float* __restrict__ res,
    float* __restrict__ C, int M, int N, int K, int mode)
{
    __shared__ float As[GBK][GBM];
    __shared__ float Ws[GBK][GBN];
    int tid = threadIdx.x;
    int m0 = blockIdx.y * GBM;
    int n0 = blockIdx.x * GBN;
    int tx = tid & 15, ty = tid >> 4;

    int lm  = tid >> 2;          // A-tile row (0..63)
    int lk4 = (tid & 3) * 4;     // A-tile k quad
    int lk  = tid >> 4;          // W-tile k row (0..15)
    int ln4 = (tid & 15) * 4;    // W-tile n quad

    float acc[4][4] = {};
    for (int k0 = 0; k0 < K; k0 += GBK) {
        float4 av = *(const float4*)(A + (size_t)(m0 + lm) * K + k0 + lk4);
        As[lk4 + 0][lm] = av.x; As[lk4 + 1][lm] = av.y;
        As[lk4 + 2][lm] = av.z; As[lk4 + 3][lm] = av.w;
        float4 wv = *(const float4*)(W + (size_t)(k0 + lk) * N + n0 + ln4);
        *(float4*)&Ws[lk][ln4] = wv;
        __syncthreads();
#pragma unroll
        for (int kk = 0; kk < GBK; kk++) {
            float4 a = *(const float4*)&As[kk][ty * 4];
            float4 w = *(const float4*)&Ws[kk][tx * 4];
            float aa[4] = {a.x, a.y, a.z, a.w};
            float ww[4] = {w.x, w.y, w.z, w.w};
#pragma unroll
            for (int i = 0; i < 4; i++)
#pragma unroll
                for (int j = 0; j < 4; j++)
                    acc[i][j] += aa[i] * ww[j];
        }
        __syncthreads();
    }
#pragma unroll
    for (int i = 0; i < 4; i++) {
        int m = m0 + ty * 4 + i;
#pragma unroll
        for (int j = 0; j < 4; j++) {
            int n = n0 + tx * 4 + j;
            float v = acc[i][j] + bias[n];
            if (mode == 1) v = fmaxf(v, 0.f);
            else if (mode == 2) v += res[(size_t)m * N + n];
            C[(size_t)m * N + n] = v;
        }
    }
}

// ---------------- QK^T : SC[bh,t,s] = 0.125 * sum_d Q[b,t,h*64+d]K[b,s,h*64+d]
__global__ __launch_bounds__(256) void qk_kernel(
    const float* __restrict__ Q, const float* __restrict__ Kt,
    float* __restrict__ SC, int Sk, int causal)
{
    int bh = blockIdx.z; int b = bh >> 3, h = bh & 7;
    int s0 = blockIdx.x * 64, t0 = blockIdx.y * 64;
    if (causal && s0 > t0 + 63) return;   // fully masked tile (never read downstream)

    __shared__ float Qs[GBK][64];
    __shared__ float Ks[GBK][64];
    int tid = threadIdx.x;
    int tx = tid & 15, ty = tid >> 4;
    int lr = tid >> 2, lk4 = (tid & 3) * 4;

    const float* Qb = Q + (size_t)b * TT * DM + h * DK;
    const float* Kb = Kt + (size_t)b * Sk * DM + h * DK;

    float acc[4][4] = {};
#pragma unroll
    for (int k0 = 0; k0 < DK; k0 += GBK) {
        float4 qv = *(const float4*)(Qb + (size_t)(t0 + lr) * DM + k0 + lk4);
        Qs[lk4 + 0][lr] = qv.x; Qs[lk4 + 1][lr] = qv.y;
        Qs[lk4 + 2][lr] = qv.z; Qs[lk4 + 3][lr] = qv.w;
        float4 kv = *(const float4*)(Kb + (size_t)(s0 + lr) * DM + k0 + lk4);
        Ks[lk4 + 0][lr] = kv.x; Ks[lk4 + 1][lr] = kv.y;
        Ks[lk4 + 2][lr] = kv.z; Ks[lk4 + 3][lr] = kv.w;
        __syncthreads();
#pragma unroll
        for (int kk = 0; kk < GBK; kk++) {
            float4 a = *(const float4*)&Qs[kk][ty * 4];
            float4 w = *(const float4*)&Ks[kk][tx * 4];
            float aa[4] = {a.x, a.y, a.z, a.w};
            float ww[4] = {w.x, w.y, w.z, w.w};
#pragma unroll
            for (int i = 0; i < 4; i++)
#pragma unroll
                for (int j = 0; j < 4; j++)
                    acc[i][j] += aa[i] * ww[j];
        }
        __syncthreads();
    }
    float* scb = SC + ((size_t)bh * TT + t0) * Sk + s0;
#pragma unroll
    for (int i = 0; i < 4; i++)
#pragma unroll
        for (int j = 0; j < 4; j++)
            scb[(size_t)(ty * 4 + i) * Sk + tx * 4 + j] = acc[i][j] * 0.125f;
}

// ---------------- Softmax over score rows (mask-aware, zero-fills masked) ----
__global__ __launch_bounds__(128) void softmax_kernel(
    float* __restrict__ SC, int Sk, int causal)
{
    int row = blockIdx.x;           // = bh*TT + t
    int t = row & (TT - 1);
    float* p = SC + (size_t)row * Sk;
    int tid = threadIdx.x;
    int slim = causal ? t + 1 : Sk;

    float lmax = -1e30f;
    for (int s = tid; s < slim; s += 128) lmax = fmaxf(lmax, p[s]);
    __shared__ float red[128];
    red[tid] = lmax; __syncthreads();
#pragma unroll
    for (int o = 64; o; o >>= 1) { if (tid < o) red[tid] = fmaxf(red[tid], red[tid + o]); __syncthreads(); }
    float mx = red[0];
    __syncthreads();

    float lsum = 0.f;
    for (int s = tid; s < slim; s += 128) {
        float e = __expf(p[s] - mx);
        p[s] = e; lsum += e;
    }
    red[tid] = lsum; __syncthreads();
#pragma unroll
    for (int o = 64; o; o >>= 1) { if (tid < o) red[tid] += red[tid + o]; __syncthreads(); }
    float inv = 1.f / red[0];
    __syncthreads();
    for (int s = tid; s < Sk; s += 128)
        p[s] = (s < slim) ? p[s] * inv : 0.f;
}

// ---------------- P @ V : O[b,t,h*64+d] = sum_s P[bh,t,s] V[b,s,h*64+d] ------
__global__ __launch_bounds__(256) void pv_kernel(
    const float* __restrict__ P, const float* __restrict__ Vt,
    float* __restrict__ O, int Sk, int causal)
{
    int bh = blockIdx.y; int b = bh >> 3, h = bh & 7;
    int t0 = blockIdx.x * 64;
    __shared__ float Ps[GBK][64];
    __shared__ float Vs[GBK][64];
    int tid = threadIdx.x;
    int tx = tid & 15, ty = tid >> 4;
    int lr = tid >> 2, lk4 = (tid & 3) * 4;
    int lk = tid >> 4, ln4 = (tid & 15) * 4;

    const float* Pb = P + ((size_t)bh * TT + t0) * Sk;
    const float* Vb = Vt + (size_t)b * Sk * DM + h * DK;

    int kend = causal ? (t0 + 64 < Sk ? t0 + 64 : Sk) : Sk;  // probs are 0 beyond
    float acc[4][4] = {};
    for (int k0 = 0; k0 < kend; k0 += GBK) {
        float4 pv = *(const float4*)(Pb + (size_t)lr * Sk + k0 + lk4);
        Ps[lk4 + 0][lr] = pv.x; Ps[lk4 + 1][lr] = pv.y;
        Ps[lk4 + 2][lr] = pv.z; Ps[lk4 + 3][lr] = pv.w;
        float4 vv = *(const float4*)(Vb + (size_t)(k0 + lk) * DM + ln4);
        *(float4*)&Vs[lk][ln4] = vv;
        __syncthreads();
#pragma unroll
        for (int kk = 0; kk < GBK; kk++) {
            float4 a = *(const float4*)&Ps[kk][ty * 4];
            float4 w = *(const float4*)&Vs[kk][tx * 4];
            float aa[4] = {a.x, a.y, a.z, a.w};
            float ww[4] = {w.x, w.y, w.z, w.w};
#pragma unroll
            for (int i = 0; i < 4; i++)
#pragma unroll
                for (int j = 0; j < 4; j++)
                    acc[i][j] += aa[i] * ww[j];
        }
        __syncthreads();
    }
#pragma unroll
    for (int i = 0; i < 4; i++)
#pragma unroll
        for (int j = 0; j < 4; j++)
            O[((size_t)b * TT + t0 + ty * 4 + i) * DM + h * DK + tx * 4 + j] = acc[i][j];
}

// ---------------- launch ------------------------------------------------------
extern "C" void kernel_launch(void* const* d_in, const int* in_sizes, int n_in,
                              void* d_out, int out_size)
{
    const float* tgt    = (const float*)d_in[0];
    const float* memory = (const float*)d_in[1];
    // d_in[2]=source_mask (all ones), d_in[3]=target_mask (tril) — fixed, hardcoded.

    // Only layer 5 affects the output (the reference loop discards `output`
    // at the top of each iteration: self-attn always re-reads `tgt`).
    const size_t OW = (size_t)LAYER * DM * DM;
    const size_t OB = (size_t)LAYER * DM;
    const float* sa_wq = (const float*)d_in[4]  + OW;
    const float* sa_wk = (const float*)d_in[5]  + OW;
    const float* sa_wv = (const float*)d_in[6]  + OW;
    const float* sa_wo = (const float*)d_in[7]  + OW;
    const float* sa_bq = (const float*)d_in[8]  + OB;
    const float* sa_bk = (const float*)d_in[9]  + OB;
    const float* sa_bv = (const float*)d_in[10] + OB;
    const float* sa_bo = (const float*)d_in[11] + OB;
    const float* ca_wq = (const float*)d_in[12] + OW;
    const float* ca_wk = (const float*)d_in[13] + OW;
    const float* ca_wv = (const float*)d_in[14] + OW;
    const float* ca_wo = (const float*)d_in[15] + OW;
    const float* ca_bq = (const float*)d_in[16] + OB;
    const float* ca_bk = (const float*)d_in[17] + OB;
    const float* ca_bv = (const float*)d_in[18] + OB;
    const float* ca_bo = (const float*)d_in[19] + OB;
    const float* ff_w1 = (const float*)d_in[20] + (size_t)LAYER * DM * FF;
    const float* ff_b1 = (const float*)d_in[21] + (size_t)LAYER * FF;
    const float* ff_w2 = (const float*)d_in[22] + (size_t)LAYER * FF * DM;
    const float* ff_b2 = (const float*)d_in[23] + OB;
    const float* ln_g  = (const float*)d_in[24];
    const float* ln_b  = (const float*)d_in[25];

    float *n_, *q_, *k_, *v_, *at_, *x_, *ff_, *sc_;
    cudaGetSymbolAddress((void**)&n_,  g_n);
    cudaGetSymbolAddress((void**)&q_,  g_q);
    cudaGetSymbolAddress((void**)&k_,  g_k);
    cudaGetSymbolAddress((void**)&v_,  g_v);
    cudaGetSymbolAddress((void**)&at_, g_at);
    cudaGetSymbolAddress((void**)&x_,  g_x);
    cudaGetSymbolAddress((void**)&ff_, g_ff);
    cudaGetSymbolAddress((void**)&sc_, g_sc);

    const int M  = BB * TT;   // 4096
    const int Mm = BB * SS;   // 8192
    dim3 gP (DM / 64, M  / 64);   // (8, 64)
    dim3 gPm(DM / 64, Mm / 64);   // (8, 128)

    // ---- self-attention block: x = tgt + SA(LN(tgt)) ----
    ln_kernel<<<M, 128>>>(tgt, ln_g, ln_b, n_);
    gemm_proj<<<gP, 256>>>(n_, sa_wq, sa_bq, nullptr, q_, M, DM, DM, 0);
    gemm_proj<<<gP, 256>>>(n_, sa_wk, sa_bk, nullptr, k_, M, DM, DM, 0);
    gemm_proj<<<gP, 256>>>(n_, sa_wv, sa_bv, nullptr, v_, M, DM, DM, 0);
    qk_kernel<<<dim3(TT / 64, TT / 64, BB * NH), 256>>>(q_, k_, sc_, TT, 1);
    softmax_kernel<<<BB * NH * TT, 128>>>(sc_, TT, 1);
    pv_kernel<<<dim3(TT / 64, BB * NH), 256>>>(sc_, v_, at_, TT, 1);
    gemm_proj<<<gP, 256>>>(at_, sa_wo, sa_bo, tgt, x_, M, DM, DM, 2);

    // ---- cross-attention block: x += CA(LN(x), memory) ----
    ln_kernel<<<M, 128>>>(x_, ln_g, ln_b, n_);
    gemm_proj<<<gP,  256>>>(n_,     ca_wq, ca_bq, nullptr, q_, M,  DM, DM, 0);
    gemm_proj<<<gPm, 256>>>(memory, ca_wk, ca_bk, nullptr, k_, Mm, DM, DM, 0);
    gemm_proj<<<gPm, 256>>>(memory, ca_wv, ca_bv, nullptr, v_, Mm, DM, DM, 0);
    qk_kernel<<<dim3(SS / 64, TT / 64, BB * NH), 256>>>(q_, k_, sc_, SS, 0);
    softmax_kernel<<<BB * NH * TT, 128>>>(sc_, SS, 0);
    pv_kernel<<<dim3(TT / 64, BB * NH), 256>>>(sc_, v_, at_, SS, 0);
    gemm_proj<<<gP, 256>>>(at_, ca_wo, ca_bo, x_, x_, M, DM, DM, 2);

    // ---- FFN block: x += W2 relu(W1 LN(x)) ----
    ln_kernel<<<M, 128>>>(x_, ln_g, ln_b, n_);
    gemm_proj<<<dim3(FF / 64, M / 64), 256>>>(n_, ff_w1, ff_b1, nullptr, ff_, M, FF, DM, 1);
    gemm_proj<<<gP, 256>>>(ff_, ff_w2, ff_b2, x_, x_, M, DM, FF, 2);

    // ---- final LN -> d_out ----
    ln_kernel<<<M, 128>>>(x_, ln_g, ln_b, (float*)d_out);
}

// round 3
// speedup vs baseline: 2.1066x; 2.1066x over previous
#include <cuda_runtime.h>
#include <cstdint>

// Problem constants
#define NH   8
#define DM   512
#define FFD  2048
#define BB   8
#define TT   512
#define SS   1024
#define LAYER 5

// ---------------- scratch (device globals) ------------------------------------
__device__ float g_n  [BB*TT*DM];
__device__ float g_q  [BB*TT*DM];
__device__ float g_k  [BB*SS*DM];
__device__ float g_v  [BB*SS*DM];
__device__ float g_vt [DM*BB*SS];            // transposed V  [D][B*S]
__device__ float g_at [BB*TT*DM];
__device__ float g_x  [BB*TT*DM];
__device__ float g_ff [BB*TT*FFD];
__device__ float g_sc [(size_t)BB*NH*TT*SS]; // scores/probs
__device__ float g_wt [8*DM*DM];             // 8 transposed 512x512 weights
__device__ float g_w1t[FFD*DM];              // [2048][512]
__device__ float g_w2t[DM*FFD];              // [512][2048]

// ---------------- helpers ------------------------------------------------------
__device__ __forceinline__ uint32_t smem_u32(const void* p) {
    uint32_t a;
    asm("{ .reg .u64 t; cvta.to.shared.u64 t, %1; cvt.u32.u64 %0, t; }" : "=r"(a) : "l"(p));
    return a;
}
__device__ __forceinline__ uint32_t f2tf(float f) {
    uint32_t u;
    asm("cvt.rna.tf32.f32 %0, %1;" : "=r"(u) : "f"(f));
    return u;
}
#define CP16(dst, src) \
    asm volatile("cp.async.cg.shared.global [%0], [%1], 16;" :: "r"(dst), "l"(src))
#define CP_COMMIT() asm volatile("cp.async.commit_group;" ::: "memory")
#define CP_WAIT1()  asm volatile("cp.async.wait_group 1;" ::: "memory")
#define CP_WAIT0()  asm volatile("cp.async.wait_group 0;" ::: "memory")

#define MMA_TF32(c, a, b) \
    asm volatile("mma.sync.aligned.m16n8k8.row.col.f32.tf32.tf32.f32 " \
        "{%0,%1,%2,%3}, {%4,%5,%6,%7}, {%8,%9}, {%0,%1,%2,%3};" \
        : "+f"((c)[0]), "+f"((c)[1]), "+f"((c)[2]), "+f"((c)[3]) \
        : "r"((a)[0]), "r"((a)[1]), "r"((a)[2]), "r"((a)[3]), "r"((b)[0]), "r"((b)[1]))

// swizzled smem float index for a [rows][32] tile
__device__ __forceinline__ int swz(int r, int c) {
    return r * 32 + ((((c >> 2) ^ (r & 7)) << 2) | (c & 3));
}

// ============ mma.sync tf32 GEMM ===============================================
// C[128-tiled, BN-tiled] = epi( A[M,K] @ B[N,K]^T )
// A row-major lda, B row-major ldb (already [N][K]).
// EPI: 0=+bias  1=relu(+bias)  2=+bias+res  3=*scale  4=none
template<int BN, int EPI>
__global__ __launch_bounds__(256) void mma_gemm(
    const float* __restrict__ A, int lda, long long sAb, long long sAh,
    const float* __restrict__ B, int ldb, long long sBb, long long sBh,
    const float* __restrict__ bias, const float* __restrict__ res,
    float* __restrict__ C, int ldc, long long sCb, long long sCh,
    int K, float scale, int causal, int kcap)
{
    constexpr int WTM = (BN == 128) ? 64 : 32;   // warp tile M
    constexpr int MW  = 128 / WTM;               // warps along M (2 or 4)
    constexpr int MF  = WTM / 16;                // m-fragments per warp
    constexpr int NF  = 4;                       // 32-wide warp N tile

    const int m0 = blockIdx.y * 128;
    const int n0 = blockIdx.x * BN;
    if (causal && n0 > m0 + 127) return;

    const int z = blockIdx.z;
    const float* Ap = A + (z >> 3) * sAb + (z & 7) * sAh;
    const float* Bp = B + (z >> 3) * sBb + (z & 7) * sBh;
    float*       Cp = C + (z >> 3) * sCb + (z & 7) * sCh;
    const float* resp = (EPI == 2) ? (res + (z >> 3) * sCb + (z & 7) * sCh) : nullptr;

    extern __shared__ float smem[];
    float* bufA[2] = { smem,            smem + 128 * 32 };
    float* bufB[2] = { smem + 2*128*32, smem + 2*128*32 + BN * 32 };
    const uint32_t uA[2] = { smem_u32(bufA[0]), smem_u32(bufA[1]) };
    const uint32_t uB[2] = { smem_u32(bufB[0]), smem_u32(bufB[1]) };

    const int tid  = threadIdx.x;
    const int lane = tid & 31;
    const int wid  = tid >> 5;
    const int wm   = wid & (MW - 1);
    const int wn   = wid / MW;
    const int laneR = lane >> 2, laneC = lane & 3;

    int Keff = K;
    if (kcap > 0) { int kk = m0 + kcap; Keff = kk < K ? kk : K; }
    const int nch = Keff >> 5;

    auto load_chunk = [&](int c) {
        const int buf = c & 1;
        const int k0 = c << 5;
#pragma unroll
        for (int i = 0; i < 4; i++) {
            int idx = tid + i * 256; int r = idx >> 3, f = idx & 7;
            CP16(uA[buf] + r * 128 + ((f ^ (r & 7)) << 4),
                 Ap + (size_t)(m0 + r) * lda + k0 + f * 4);
        }
#pragma unroll
        for (int i = 0; i < BN / 32; i++) {
            int idx = tid + i * 256; int r = idx >> 3, f = idx & 7;
            CP16(uB[buf] + r * 128 + ((f ^ (r & 7)) << 4),
                 Bp + (size_t)(n0 + r) * ldb + k0 + f * 4);
        }
        CP_COMMIT();
    };

    float acc[MF][NF][4] = {};

    load_chunk(0);
    for (int c = 0; c < nch; c++) {
        if (c + 1 < nch) { load_chunk(c + 1); CP_WAIT1(); }
        else             { CP_WAIT0(); }
        __syncthreads();
        const float* sA = bufA[c & 1];
        const float* sB = bufB[c & 1];
#pragma unroll
        for (int ks = 0; ks < 4; ks++) {
            uint32_t af[MF][4];
#pragma unroll
            for (int mf = 0; mf < MF; mf++) {
                int r = wm * WTM + mf * 16 + laneR;
                int cc = ks * 8 + laneC;
                af[mf][0] = f2tf(sA[swz(r,     cc)]);
                af[mf][1] = f2tf(sA[swz(r + 8, cc)]);
                af[mf][2] = f2tf(sA[swz(r,     cc + 4)]);
                af[mf][3] = f2tf(sA[swz(r + 8, cc + 4)]);
            }
            uint32_t bf[NF][2];
#pragma unroll
            for (int nf = 0; nf < NF; nf++) {
                int n = wn * 32 + nf * 8 + laneR;
                int cc = ks * 8 + laneC;
                bf[nf][0] = f2tf(sB[swz(n, cc)]);
                bf[nf][1] = f2tf(sB[swz(n, cc + 4)]);
            }
#pragma unroll
            for (int mf = 0; mf < MF; mf++)
#pragma unroll
                for (int nf = 0; nf < NF; nf++)
                    MMA_TF32(acc[mf][nf], af[mf], bf[nf]);
        }
        __syncthreads();
    }

    // ---- epilogue: direct reg -> gmem, fused ops ----
#pragma unroll
    for (int mf = 0; mf < MF; mf++) {
#pragma unroll
        for (int nf = 0; nf < NF; nf++) {
            int r  = m0 + wm * WTM + mf * 16 + laneR;
            int cc = n0 + wn * 32 + nf * 8 + laneC * 2;
            float v0 = acc[mf][nf][0], v1 = acc[mf][nf][1];
            float v2 = acc[mf][nf][2], v3 = acc[mf][nf][3];
            if (EPI <= 2) {
                float2 bb = *(const float2*)(bias + cc);
                v0 += bb.x; v1 += bb.y; v2 += bb.x; v3 += bb.y;
            }
            if (EPI == 1) {
                v0 = fmaxf(v0, 0.f); v1 = fmaxf(v1, 0.f);
                v2 = fmaxf(v2, 0.f); v3 = fmaxf(v3, 0.f);
            }
            if (EPI == 2) {
                float2 r0 = *(const float2*)(resp + (size_t)r * ldc + cc);
                float2 r1 = *(const float2*)(resp + (size_t)(r + 8) * ldc + cc);
                v0 += r0.x; v1 += r0.y; v2 += r1.x; v3 += r1.y;
            }
            if (EPI == 3) { v0 *= scale; v1 *= scale; v2 *= scale; v3 *= scale; }
            *(float2*)(Cp + (size_t)r * ldc + cc)       = make_float2(v0, v1);
            *(float2*)(Cp + (size_t)(r + 8) * ldc + cc) = make_float2(v2, v3);
        }
    }
}

// ---------------- transpose kernels -------------------------------------------
__global__ __launch_bounds__(256) void transpose_one(
    const float* __restrict__ src, float* __restrict__ dst, int R, int C)
{
    __shared__ float t[32][33];
    int tx = threadIdx.x, ty = threadIdx.y;
    int x = blockIdx.x * 32 + tx;
    int y = blockIdx.y * 32;
#pragma unroll
    for (int i = 0; i < 4; i++)
        t[ty + i * 8][tx] = src[(size_t)(y + ty + i * 8) * C + x];
    __syncthreads();
    int x2 = blockIdx.y * 32 + tx;
    int y2 = blockIdx.x * 32;
#pragma unroll
    for (int i = 0; i < 4; i++)
        dst[(size_t)(y2 + ty + i * 8) * R + x2] = t[tx][ty + i * 8];
}

struct TP8 { const float* s[8]; float* d[8]; };
__global__ __launch_bounds__(256) void transpose8(TP8 p)   // 8x [512][512]
{
    __shared__ float t[32][33];
    const float* src = p.s[blockIdx.z];
    float* dst = p.d[blockIdx.z];
    int tx = threadIdx.x, ty = threadIdx.y;
    int x = blockIdx.x * 32 + tx;
    int y = blockIdx.y * 32;
#pragma unroll
    for (int i = 0; i < 4; i++)
        t[ty + i * 8][tx] = src[(size_t)(y + ty + i * 8) * DM + x];
    __syncthreads();
    int x2 = blockIdx.y * 32 + tx;
    int y2 = blockIdx.x * 32;
#pragma unroll
    for (int i = 0; i < 4; i++)
        dst[(size_t)(y2 + ty + i * 8) * DM + x2] = t[tx][ty + i * 8];
}

// ---------------- LayerNorm ---------------------------------------------------
__global__ __launch_bounds__(128) void ln_kernel(
    const float* __restrict__ x, const float* __restrict__ g,
    const float* __restrict__ b, float* __restrict__ out)
{
    int row = blockIdx.x;
    const float* xr = x + (size_t)row * DM;
    float* orow = out + (size_t)row * DM;
    int tid = threadIdx.x;

    float vals[4];
    float s = 0.f, s2 = 0.f;
#pragma unroll
    for (int i = 0; i < 4; i++) {
        float v = xr[tid + i * 128];
        vals[i] = v; s += v; s2 += v * v;
    }
#pragma unroll
    for (int o = 16; o; o >>= 1) {
        s  += __shfl_down_sync(0xffffffffu, s,  o);
        s2 += __shfl_down_sync(0xffffffffu, s2, o);
    }
    __shared__ float rs[4], rs2[4];
    int wid = tid >> 5, lane = tid & 31;
    if (lane == 0) { rs[wid] = s; rs2[wid] = s2; }
    __syncthreads();
    if (tid == 0) {
        float a = 0.f, a2 = 0.f;
#pragma unroll
        for (int w = 0; w < 4; w++) { a += rs[w]; a2 += rs2[w]; }
        rs[0] = a; rs2[0] = a2;
    }
    __syncthreads();
    float mean = rs[0] * (1.0f / DM);
    float var  = rs2[0] * (1.0f / DM) - mean * mean;
    float inv  = rsqrtf(var + 1e-5f);
#pragma unroll
    for (int i = 0; i < 4; i++) {
        int c = tid + i * 128;
        orow[c] = (vals[i] - mean) * inv * g[c] + b[c];
    }
}

// ---------------- Softmax ------------------------------------------------------
__global__ __launch_bounds__(128) void softmax_kernel(
    float* __restrict__ SC, int Sk, int causal)
{
    int row = blockIdx.x;           // bh*TT + t
    int t = row & (TT - 1);
    float* p = SC + (size_t)row * Sk;
    int tid = threadIdx.x;
    int slim = causal ? t + 1 : Sk;

    float lmax = -1e30f;
    for (int s = tid; s < slim; s += 128) lmax = fmaxf(lmax, p[s]);
    __shared__ float red[128];
    red[tid] = lmax; __syncthreads();
#pragma unroll
    for (int o = 64; o; o >>= 1) { if (tid < o) red[tid] = fmaxf(red[tid], red[tid + o]); __syncthreads(); }
    float mx = red[0];
    __syncthreads();

    float lsum = 0.f;
    for (int s = tid; s < slim; s += 128) {
        float e = __expf(p[s] - mx);
        p[s] = e; lsum += e;
    }
    red[tid] = lsum; __syncthreads();
#pragma unroll
    for (int o = 64; o; o >>= 1) { if (tid < o) red[tid] += red[tid + o]; __syncthreads(); }
    float inv = 1.f / red[0];
    __syncthreads();
    for (int s = tid; s < Sk; s += 128)
        p[s] = (s < slim) ? p[s] * inv : 0.f;
}

// ---------------- launch -------------------------------------------------------
extern "C" void kernel_launch(void* const* d_in, const int* in_sizes, int n_in,
                              void* d_out, int out_size)
{
    const float* tgt    = (const float*)d_in[0];
    const float* memory = (const float*)d_in[1];

    const size_t OW = (size_t)LAYER * DM * DM;
    const size_t OB = (size_t)LAYER * DM;
    const float* sa_wq = (const float*)d_in[4]  + OW;
    const float* sa_wk = (const float*)d_in[5]  + OW;
    const float* sa_wv = (const float*)d_in[6]  + OW;
    const float* sa_wo = (const float*)d_in[7]  + OW;
    const float* sa_bq = (const float*)d_in[8]  + OB;
    const float* sa_bk = (const float*)d_in[9]  + OB;
    const float* sa_bv = (const float*)d_in[10] + OB;
    const float* sa_bo = (const float*)d_in[11] + OB;
    const float* ca_wq = (const float*)d_in[12] + OW;
    const float* ca_wk = (const float*)d_in[13] + OW;
    const float* ca_wv = (const float*)d_in[14] + OW;
    const float* ca_wo = (const float*)d_in[15] + OW;
    const float* ca_bq = (const float*)d_in[16] + OB;
    const float* ca_bk = (const float*)d_in[17] + OB;
    const float* ca_bv = (const float*)d_in[18] + OB;
    const float* ca_bo = (const float*)d_in[19] + OB;
    const float* ff_w1 = (const float*)d_in[20] + (size_t)LAYER * DM * FFD;
    const float* ff_b1 = (const float*)d_in[21] + (size_t)LAYER * FFD;
    const float* ff_w2 = (const float*)d_in[22] + (size_t)LAYER * FFD * DM;
    const float* ff_b2 = (const float*)d_in[23] + OB;
    const float* ln_g  = (const float*)d_in[24];
    const float* ln_b  = (const float*)d_in[25];

    float *n_, *q_, *k_, *v_, *vt_, *at_, *x_, *ff_, *sc_, *wt_, *w1t_, *w2t_;
    cudaGetSymbolAddress((void**)&n_,   g_n);
    cudaGetSymbolAddress((void**)&q_,   g_q);
    cudaGetSymbolAddress((void**)&k_,   g_k);
    cudaGetSymbolAddress((void**)&v_,   g_v);
    cudaGetSymbolAddress((void**)&vt_,  g_vt);
    cudaGetSymbolAddress((void**)&at_,  g_at);
    cudaGetSymbolAddress((void**)&x_,   g_x);
    cudaGetSymbolAddress((void**)&ff_,  g_ff);
    cudaGetSymbolAddress((void**)&sc_,  g_sc);
    cudaGetSymbolAddress((void**)&wt_,  g_wt);
    cudaGetSymbolAddress((void**)&w1t_, g_w1t);
    cudaGetSymbolAddress((void**)&w2t_, g_w2t);

    const int S128 = 2 * (128 * 32 + 128 * 32) * 4;   // 65536
    const int S64  = 2 * (128 * 32 + 64  * 32) * 4;   // 49152
    cudaFuncSetAttribute(mma_gemm<128,0>, cudaFuncAttributeMaxDynamicSharedMemorySize, S128);
    cudaFuncSetAttribute(mma_gemm<128,1>, cudaFuncAttributeMaxDynamicSharedMemorySize, S128);
    cudaFuncSetAttribute(mma_gemm<128,2>, cudaFuncAttributeMaxDynamicSharedMemorySize, S128);
    cudaFuncSetAttribute(mma_gemm<128,3>, cudaFuncAttributeMaxDynamicSharedMemorySize, S128);
    cudaFuncSetAttribute(mma_gemm<64,4>,  cudaFuncAttributeMaxDynamicSharedMemorySize, S64);

    const int M = BB * TT;                          // 4096
    const long long LTT = (long long)TT * DM;
    const long long LSS = (long long)SS * DM;

    // transposed weight slots
    float* wqT = wt_ + 0 * DM * DM;
    float* wkT = wt_ + 1 * DM * DM;
    float* wvT = wt_ + 2 * DM * DM;
    float* woT = wt_ + 3 * DM * DM;
    float* cqT = wt_ + 4 * DM * DM;
    float* ckT = wt_ + 5 * DM * DM;
    float* cvT = wt_ + 6 * DM * DM;
    float* coT = wt_ + 7 * DM * DM;

    // ---- weight transposes (one batched launch + 2) ----
    TP8 tp;
    tp.s[0]=sa_wq; tp.d[0]=wqT;  tp.s[1]=sa_wk; tp.d[1]=wkT;
    tp.s[2]=sa_wv; tp.d[2]=wvT;  tp.s[3]=sa_wo; tp.d[3]=woT;
    tp.s[4]=ca_wq; tp.d[4]=cqT;  tp.s[5]=ca_wk; tp.d[5]=ckT;
    tp.s[6]=ca_wv; tp.d[6]=cvT;  tp.s[7]=ca_wo; tp.d[7]=coT;
    transpose8<<<dim3(16,16,8), dim3(32,8)>>>(tp);
    transpose_one<<<dim3(FFD/32, DM/32),  dim3(32,8)>>>(ff_w1, w1t_, DM,  FFD);
    transpose_one<<<dim3(DM/32,  FFD/32), dim3(32,8)>>>(ff_w2, w2t_, FFD, DM);

    // ---- self-attention: x = tgt + SA(LN(tgt)) ----
    ln_kernel<<<M, 128>>>(tgt, ln_g, ln_b, n_);
    mma_gemm<128,0><<<dim3(4,32,1),256,S128>>>(n_,DM,0,0, wqT,DM,0,0, sa_bq,nullptr, q_,DM,0,0, DM,1.f,0,0);
    mma_gemm<128,0><<<dim3(4,32,1),256,S128>>>(n_,DM,0,0, wkT,DM,0,0, sa_bk,nullptr, k_,DM,0,0, DM,1.f,0,0);
    mma_gemm<128,0><<<dim3(4,32,1),256,S128>>>(n_,DM,0,0, wvT,DM,0,0, sa_bv,nullptr, v_,DM,0,0, DM,1.f,0,0);
    transpose_one<<<dim3(DM/32, M/32), dim3(32,8)>>>(v_, vt_, M, DM);   // vt [512][4096]
    mma_gemm<128,3><<<dim3(4,4,64),256,S128>>>(
        q_,DM,LTT,64, k_,DM,LTT,64, nullptr,nullptr,
        sc_,TT,(long long)NH*TT*TT,(long long)TT*TT, 64,0.125f,1,0);
    softmax_kernel<<<BB*NH*TT, 128>>>(sc_, TT, 1);
    mma_gemm<64,4><<<dim3(1,4,64),256,S64>>>(
        sc_,TT,(long long)NH*TT*TT,(long long)TT*TT,
        vt_,M,(long long)TT,(long long)64*M, nullptr,nullptr,
        at_,DM,LTT,64, TT,1.f,0,128);
    mma_gemm<128,2><<<dim3(4,32,1),256,S128>>>(at_,DM,0,0, woT,DM,0,0, sa_bo,tgt, x_,DM,0,0, DM,1.f,0,0);

    // ---- cross-attention: x += CA(LN(x), memory) ----
    ln_kernel<<<M, 128>>>(x_, ln_g, ln_b, n_);
    mma_gemm<128,0><<<dim3(4,32,1),256,S128>>>(n_,DM,0,0, cqT,DM,0,0, ca_bq,nullptr, q_,DM,0,0, DM,1.f,0,0);
    mma_gemm<128,0><<<dim3(4,64,1),256,S128>>>(memory,DM,0,0, ckT,DM,0,0, ca_bk,nullptr, k_,DM,0,0, DM,1.f,0,0);
    mma_gemm<128,0><<<dim3(4,64,1),256,S128>>>(memory,DM,0,0, cvT,DM,0,0, ca_bv,nullptr, v_,DM,0,0, DM,1.f,0,0);
    transpose_one<<<dim3(DM/32, (BB*SS)/32), dim3(32,8)>>>(v_, vt_, BB*SS, DM);  // vt [512][8192]
    mma_gemm<128,3><<<dim3(8,4,64),256,S128>>>(
        q_,DM,LTT,64, k_,DM,LSS,64, nullptr,nullptr,
        sc_,SS,(long long)NH*TT*SS,(long long)TT*SS, 64,0.125f,0,0);
    softmax_kernel<<<BB*NH*TT, 128>>>(sc_, SS, 0);
    mma_gemm<64,4><<<dim3(1,4,64),256,S64>>>(
        sc_,SS,(long long)NH*TT*SS,(long long)TT*SS,
        vt_,BB*SS,(long long)SS,(long long)64*BB*SS, nullptr,nullptr,
        at_,DM,LTT,64, SS,1.f,0,0);
    mma_gemm<128,2><<<dim3(4,32,1),256,S128>>>(at_,DM,0,0, coT,DM,0,0, ca_bo,x_, x_,DM,0,0, DM,1.f,0,0);

    // ---- FFN: x += W2 relu(W1 LN(x)) ----
    ln_kernel<<<M, 128>>>(x_, ln_g, ln_b, n_);
    mma_gemm<128,1><<<dim3(16,32,1),256,S128>>>(n_,DM,0,0, w1t_,DM,0,0, ff_b1,nullptr, ff_,FFD,0,0, DM,1.f,0,0);
    mma_gemm<128,2><<<dim3(4,32,1),256,S128>>>(ff_,FFD,0,0, w2t_,FFD,0,0, ff_b2,x_, x_,DM,0,0, FFD,1.f,0,0);

    // ---- final LN -> out ----
    ln_kernel<<<M, 128>>>(x_, ln_g, ln_b, (float*)d_out);
}

// round 4
// speedup vs baseline: 2.6520x; 1.2589x over previous
#include <cuda_runtime.h>
#include <cstdint>

// Problem constants
#define NH   8
#define DM   512
#define FFD  2048
#define BB   8
#define TT   512
#define SS   1024
#define LAYER 5

// ---------------- scratch (device globals) ------------------------------------
__device__ float g_n  [BB*TT*DM];
__device__ float g_q  [BB*TT*DM];
__device__ float g_k  [BB*SS*DM];
__device__ float g_v  [BB*SS*DM];
__device__ float g_vt [DM*BB*SS];            // transposed V  [D][B*S]
__device__ float g_at [BB*TT*DM];
__device__ float g_x  [BB*TT*DM];
__device__ float g_ff [BB*TT*FFD];
__device__ float g_wt [8*DM*DM];             // 8 transposed 512x512 weights
__device__ float g_w1t[FFD*DM];              // [2048][512]
__device__ float g_w2t[DM*FFD];              // [512][2048]

// ---------------- helpers ------------------------------------------------------
__device__ __forceinline__ uint32_t smem_u32(const void* p) {
    uint32_t a;
    asm("{ .reg .u64 t; cvta.to.shared.u64 t, %1; cvt.u32.u64 %0, t; }" : "=r"(a) : "l"(p));
    return a;
}
__device__ __forceinline__ uint32_t f2tf(float f) {
    uint32_t u;
    asm("cvt.rna.tf32.f32 %0, %1;" : "=r"(u) : "f"(f));
    return u;
}
#define CP16(dst, src) \
    asm volatile("cp.async.cg.shared.global [%0], [%1], 16;" :: "r"(dst), "l"(src))
#define CP_COMMIT() asm volatile("cp.async.commit_group;" ::: "memory")
#define CP_WAIT1()  asm volatile("cp.async.wait_group 1;" ::: "memory")
#define CP_WAIT0()  asm volatile("cp.async.wait_group 0;" ::: "memory")

#define MMA_TF32(c, a, b) \
    asm volatile("mma.sync.aligned.m16n8k8.row.col.f32.tf32.tf32.f32 " \
        "{%0,%1,%2,%3}, {%4,%5,%6,%7}, {%8,%9}, {%0,%1,%2,%3};" \
        : "+f"((c)[0]), "+f"((c)[1]), "+f"((c)[2]), "+f"((c)[3]) \
        : "r"((a)[0]), "r"((a)[1]), "r"((a)[2]), "r"((a)[3]), "r"((b)[0]), "r"((b)[1]))

// swizzled smem float index for a [rows][32] panel
__device__ __forceinline__ int swz(int r, int c) {
    return r * 32 + ((((c >> 2) ^ (r & 7)) << 2) | (c & 3));
}

// ============ mma.sync tf32 GEMM ===============================================
// C[128-tiled, BN-tiled] = epi( A[M,K] @ B[N,K]^T ),  B already [N][K] row-major
// EPI: 0=+bias  1=relu(+bias)  2=+bias+res
template<int BN, int EPI>
__global__ __launch_bounds__(256) void mma_gemm(
    const float* __restrict__ A, int lda,
    const float* __restrict__ B, int ldb,
    const float* __restrict__ bias, const float* __restrict__ res,
    float* __restrict__ C, int ldc, int K)
{
    constexpr int WTM = 64;                      // warp tile M
    constexpr int MW  = 2;                       // warps along M
    constexpr int MF  = WTM / 16;
    constexpr int NF  = 4;

    const int m0 = blockIdx.y * 128;
    const int n0 = blockIdx.x * BN;

    extern __shared__ float smem[];
    float* bufA[2] = { smem,            smem + 128 * 32 };
    float* bufB[2] = { smem + 2*128*32, smem + 2*128*32 + BN * 32 };
    const uint32_t uA[2] = { smem_u32(bufA[0]), smem_u32(bufA[1]) };
    const uint32_t uB[2] = { smem_u32(bufB[0]), smem_u32(bufB[1]) };

    const int tid  = threadIdx.x;
    const int lane = tid & 31;
    const int wid  = tid >> 5;
    const int wm   = wid & (MW - 1);
    const int wn   = wid / MW;
    const int laneR = lane >> 2, laneC = lane & 3;

    const int nch = K >> 5;

    auto load_chunk = [&](int c) {
        const int buf = c & 1;
        const int k0 = c << 5;
#pragma unroll
        for (int i = 0; i < 4; i++) {
            int idx = tid + i * 256; int r = idx >> 3, f = idx & 7;
            CP16(uA[buf] + r * 128 + ((f ^ (r & 7)) << 4),
                 A + (size_t)(m0 + r) * lda + k0 + f * 4);
        }
#pragma unroll
        for (int i = 0; i < BN / 32; i++) {
            int idx = tid + i * 256; int r = idx >> 3, f = idx & 7;
            CP16(uB[buf] + r * 128 + ((f ^ (r & 7)) << 4),
                 B + (size_t)(n0 + r) * ldb + k0 + f * 4);
        }
        CP_COMMIT();
    };

    float acc[MF][NF][4] = {};

    load_chunk(0);
    for (int c = 0; c < nch; c++) {
        if (c + 1 < nch) { load_chunk(c + 1); CP_WAIT1(); }
        else             { CP_WAIT0(); }
        __syncthreads();
        const float* sA = bufA[c & 1];
        const float* sB = bufB[c & 1];
#pragma unroll
        for (int ks = 0; ks < 4; ks++) {
            uint32_t af[MF][4];
#pragma unroll
            for (int mf = 0; mf < MF; mf++) {
                int r = wm * WTM + mf * 16 + laneR;
                int cc = ks * 8 + laneC;
                af[mf][0] = f2tf(sA[swz(r,     cc)]);
                af[mf][1] = f2tf(sA[swz(r + 8, cc)]);
                af[mf][2] = f2tf(sA[swz(r,     cc + 4)]);
                af[mf][3] = f2tf(sA[swz(r + 8, cc + 4)]);
            }
            uint32_t bf[NF][2];
#pragma unroll
            for (int nf = 0; nf < NF; nf++) {
                int n = wn * 32 + nf * 8 + laneR;
                int cc = ks * 8 + laneC;
                bf[nf][0] = f2tf(sB[swz(n, cc)]);
                bf[nf][1] = f2tf(sB[swz(n, cc + 4)]);
            }
#pragma unroll
            for (int mf = 0; mf < MF; mf++)
#pragma unroll
                for (int nf = 0; nf < NF; nf++)
                    MMA_TF32(acc[mf][nf], af[mf], bf[nf]);
        }
        __syncthreads();
    }

#pragma unroll
    for (int mf = 0; mf < MF; mf++) {
#pragma unroll
        for (int nf = 0; nf < NF; nf++) {
            int r  = m0 + wm * WTM + mf * 16 + laneR;
            int cc = n0 + wn * 32 + nf * 8 + laneC * 2;
            float v0 = acc[mf][nf][0], v1 = acc[mf][nf][1];
            float v2 = acc[mf][nf][2], v3 = acc[mf][nf][3];
            float2 bb = *(const float2*)(bias + cc);
            v0 += bb.x; v1 += bb.y; v2 += bb.x; v3 += bb.y;
            if (EPI == 1) {
                v0 = fmaxf(v0, 0.f); v1 = fmaxf(v1, 0.f);
                v2 = fmaxf(v2, 0.f); v3 = fmaxf(v3, 0.f);
            }
            if (EPI == 2) {
                float2 r0 = *(const float2*)(res + (size_t)r * ldc + cc);
                float2 r1 = *(const float2*)(res + (size_t)(r + 8) * ldc + cc);
                v0 += r0.x; v1 += r0.y; v2 += r1.x; v3 += r1.y;
            }
            *(float2*)(C + (size_t)r * ldc + cc)       = make_float2(v0, v1);
            *(float2*)(C + (size_t)(r + 8) * ldc + cc) = make_float2(v2, v3);
        }
    }
}

// ============ fused flash attention (tf32 mma, online softmax) =================
// Q [B*T][512] (head h at cols h*64), K [B*S][512], Vt [512][B*S] transposed.
// O [B*T][512]. Block: 256 thr, tile 128 q-rows x full head. Chunk = 64 s-rows.
template<int CAUSAL>
__global__ __launch_bounds__(256) void flash_attn(
    const float* __restrict__ Q, const float* __restrict__ Kg,
    const float* __restrict__ Vt, float* __restrict__ O, int Slen)
{
    extern __shared__ float sm[];
    float* sQ = sm;                 // 2 panels x 128x32 = 8192 floats
    float* sK = sm + 8192;          // 2 bufs x (2 panels x 64x32) = 8192
    float* sV = sm + 16384;         // 8192
    float* sP = sm + 24576;         // 8 warps x 16x64 = 8192

    const int mt = blockIdx.x, bh = blockIdx.y;
    const int b = bh >> 3, h = bh & 7;
    const int m0 = mt * 128;
    const int tid = threadIdx.x, lane = tid & 31, wid = tid >> 5;
    const int laneR = lane >> 2, laneC = lane & 3;

    const float* Qp = Q + ((size_t)b * TT + m0) * DM + h * 64;
    const float* Kp = Kg + (size_t)b * Slen * DM + h * 64;
    const float* Vp = Vt + (size_t)(h * 64) * (BB * Slen) + (size_t)b * Slen;
    float* Op = O + ((size_t)b * TT + m0) * DM + h * 64;

    const uint32_t uQ = smem_u32(sQ), uK = smem_u32(sK), uV = smem_u32(sV);

    // Q tile: 128 rows x 64 floats -> 2048 cp16 (8/thread)
#pragma unroll
    for (int i = 0; i < 8; i++) {
        int idx = tid + i * 256;
        int r = idx >> 4, f = idx & 15;
        int panel = f >> 3, fo = f & 7;
        CP16(uQ + (panel * 4096 + r * 32 + ((fo ^ (r & 7)) << 2)) * 4,
             Qp + (size_t)r * DM + f * 4);
    }

    auto load_kv = [&](int c) {
        const int buf = c & 1;
        const int s0 = c * 64;
#pragma unroll
        for (int i = 0; i < 4; i++) {
            int idx = tid + i * 256;
            int r = idx >> 4, f = idx & 15;
            int panel = f >> 3, fo = f & 7;
            CP16(uK + (buf * 4096 + panel * 2048 + r * 32 + ((fo ^ (r & 7)) << 2)) * 4,
                 Kp + (size_t)(s0 + r) * DM + f * 4);
        }
#pragma unroll
        for (int i = 0; i < 4; i++) {
            int idx = tid + i * 256;
            int r = idx >> 4, f = idx & 15;       // r = d row, f = s-group
            int panel = f >> 3, fo = f & 7;
            CP16(uV + (buf * 4096 + panel * 2048 + r * 32 + ((fo ^ (r & 7)) << 2)) * 4,
                 Vp + (size_t)r * (BB * Slen) + s0 + f * 4);
        }
        CP_COMMIT();
    };

    const int nch = CAUSAL ? (m0 + 128) / 64 : Slen / 64;
    const int wr0 = wid * 16;
    float mr0 = -1e30f, mr1 = -1e30f, l0 = 0.f, l1 = 0.f;
    float oacc[8][4] = {};
    float* sPw = sP + wid * 1024;   // warp-private [16][64] as 2 panels of 512

    load_kv(0);
    for (int c = 0; c < nch; c++) {
        if (c + 1 < nch) { load_kv(c + 1); CP_WAIT1(); }
        else             { CP_WAIT0(); }
        __syncthreads();
        const int s0 = c * 64;
        const bool active = !CAUSAL || (s0 <= m0 + wr0 + 15);
        if (active) {
            const float* cK = sK + (c & 1) * 4096;
            const float* cV = sV + (c & 1) * 4096;

            // ---- S = Q @ K^T ----
            float sacc[8][4] = {};
#pragma unroll
            for (int ks = 0; ks < 8; ks++) {
                int kk = ks * 8 + laneC;
                int pa = kk >> 5, ca = kk & 31;
                uint32_t af[4];
                {
                    const float* qp = sQ + pa * 4096;
                    int r0 = wr0 + laneR;
                    af[0] = f2tf(qp[swz(r0,     ca)]);
                    af[1] = f2tf(qp[swz(r0 + 8, ca)]);
                    af[2] = f2tf(qp[swz(r0,     ca + 4)]);
                    af[3] = f2tf(qp[swz(r0 + 8, ca + 4)]);
                }
                const float* kp = cK + pa * 2048;
#pragma unroll
                for (int nf = 0; nf < 8; nf++) {
                    uint32_t bf[2];
                    int n = nf * 8 + laneR;
                    bf[0] = f2tf(kp[swz(n, ca)]);
                    bf[1] = f2tf(kp[swz(n, ca + 4)]);
                    MMA_TF32(sacc[nf], af, bf);
                }
            }

            // ---- scale + mask + online softmax ----
            const float SCL = 0.125f;
            const int t0g = m0 + wr0 + laneR;
            float rmax0 = -1e30f, rmax1 = -1e30f;
#pragma unroll
            for (int nf = 0; nf < 8; nf++) {
                int sg = s0 + nf * 8 + 2 * laneC;
                float v0 = sacc[nf][0] * SCL, v1 = sacc[nf][1] * SCL;
                float v2 = sacc[nf][2] * SCL, v3 = sacc[nf][3] * SCL;
                if (CAUSAL) {
                    if (sg     > t0g)     v0 = -1e30f;
                    if (sg + 1 > t0g)     v1 = -1e30f;
                    if (sg     > t0g + 8) v2 = -1e30f;
                    if (sg + 1 > t0g + 8) v3 = -1e30f;
                }
                sacc[nf][0] = v0; sacc[nf][1] = v1;
                sacc[nf][2] = v2; sacc[nf][3] = v3;
                rmax0 = fmaxf(rmax0, fmaxf(v0, v1));
                rmax1 = fmaxf(rmax1, fmaxf(v2, v3));
            }
            rmax0 = fmaxf(rmax0, __shfl_xor_sync(0xffffffffu, rmax0, 1));
            rmax0 = fmaxf(rmax0, __shfl_xor_sync(0xffffffffu, rmax0, 2));
            rmax1 = fmaxf(rmax1, __shfl_xor_sync(0xffffffffu, rmax1, 1));
            rmax1 = fmaxf(rmax1, __shfl_xor_sync(0xffffffffu, rmax1, 2));
            float mn0 = fmaxf(mr0, rmax0), mn1 = fmaxf(mr1, rmax1);
            float al0 = __expf(mr0 - mn0), al1 = __expf(mr1 - mn1);
            mr0 = mn0; mr1 = mn1;

            float rs0 = 0.f, rs1 = 0.f;
#pragma unroll
            for (int nf = 0; nf < 8; nf++) {
                float e0 = __expf(sacc[nf][0] - mn0);
                float e1 = __expf(sacc[nf][1] - mn0);
                float e2 = __expf(sacc[nf][2] - mn1);
                float e3 = __expf(sacc[nf][3] - mn1);
                rs0 += e0 + e1; rs1 += e2 + e3;
                int cc = nf * 8 + 2 * laneC;
                int pa = cc >> 5, ca = cc & 31;
                *(float2*)&sPw[pa * 512 + swz(laneR,     ca)] = make_float2(e0, e1);
                *(float2*)&sPw[pa * 512 + swz(laneR + 8, ca)] = make_float2(e2, e3);
            }
            rs0 += __shfl_xor_sync(0xffffffffu, rs0, 1);
            rs0 += __shfl_xor_sync(0xffffffffu, rs0, 2);
            rs1 += __shfl_xor_sync(0xffffffffu, rs1, 1);
            rs1 += __shfl_xor_sync(0xffffffffu, rs1, 2);
            l0 = l0 * al0 + rs0;
            l1 = l1 * al1 + rs1;
#pragma unroll
            for (int nf = 0; nf < 8; nf++) {
                oacc[nf][0] *= al0; oacc[nf][1] *= al0;
                oacc[nf][2] *= al1; oacc[nf][3] *= al1;
            }
            __syncwarp();

            // ---- O += P @ V ----
#pragma unroll
            for (int ks = 0; ks < 8; ks++) {
                int kk = ks * 8 + laneC;
                int pa = kk >> 5, ca = kk & 31;
                uint32_t af[4];
                const float* pp = sPw + pa * 512;
                af[0] = f2tf(pp[swz(laneR,     ca)]);
                af[1] = f2tf(pp[swz(laneR + 8, ca)]);
                af[2] = f2tf(pp[swz(laneR,     ca + 4)]);
                af[3] = f2tf(pp[swz(laneR + 8, ca + 4)]);
                const float* vp = cV + pa * 2048;
#pragma unroll
                for (int nf = 0; nf < 8; nf++) {
                    uint32_t bf[2];
                    int n = nf * 8 + laneR;
                    bf[0] = f2tf(vp[swz(n, ca)]);
                    bf[1] = f2tf(vp[swz(n, ca + 4)]);
                    MMA_TF32(oacc[nf], af, bf);
                }
            }
        }
        __syncthreads();
    }

    const float inv0 = 1.f / l0, inv1 = 1.f / l1;
#pragma unroll
    for (int nf = 0; nf < 8; nf++) {
        int cc = nf * 8 + 2 * laneC;
        int r = wr0 + laneR;
        *(float2*)(Op + (size_t)r * DM + cc) =
            make_float2(oacc[nf][0] * inv0, oacc[nf][1] * inv0);
        *(float2*)(Op + (size_t)(r + 8) * DM + cc) =
            make_float2(oacc[nf][2] * inv1, oacc[nf][3] * inv1);
    }
}

// ---------------- transpose kernels -------------------------------------------
__global__ __launch_bounds__(256) void transpose_one(
    const float* __restrict__ src, float* __restrict__ dst, int R, int C)
{
    __shared__ float t[32][33];
    int tx = threadIdx.x, ty = threadIdx.y;
    int x = blockIdx.x * 32 + tx;
    int y = blockIdx.y * 32;
#pragma unroll
    for (int i = 0; i < 4; i++)
        t[ty + i * 8][tx] = src[(size_t)(y + ty + i * 8) * C + x];
    __syncthreads();
    int x2 = blockIdx.y * 32 + tx;
    int y2 = blockIdx.x * 32;
#pragma unroll
    for (int i = 0; i < 4; i++)
        dst[(size_t)(y2 + ty + i * 8) * R + x2] = t[tx][ty + i * 8];
}

struct TP8 { const float* s[8]; float* d[8]; };
__global__ __launch_bounds__(256) void transpose8(TP8 p)
{
    __shared__ float t[32][33];
    const float* src = p.s[blockIdx.z];
    float* dst = p.d[blockIdx.z];
    int tx = threadIdx.x, ty = threadIdx.y;
    int x = blockIdx.x * 32 + tx;
    int y = blockIdx.y * 32;
#pragma unroll
    for (int i = 0; i < 4; i++)
        t[ty + i * 8][tx] = src[(size_t)(y + ty + i * 8) * DM + x];
    __syncthreads();
    int x2 = blockIdx.y * 32 + tx;
    int y2 = blockIdx.x * 32;
#pragma unroll
    for (int i = 0; i < 4; i++)
        dst[(size_t)(y2 + ty + i * 8) * DM + x2] = t[tx][ty + i * 8];
}

// ---------------- LayerNorm ---------------------------------------------------
__global__ __launch_bounds__(128) void ln_kernel(
    const float* __restrict__ x, const float* __restrict__ g,
    const float* __restrict__ b, float* __restrict__ out)
{
    int row = blockIdx.x;
    const float* xr = x + (size_t)row * DM;
    float* orow = out + (size_t)row * DM;
    int tid = threadIdx.x;

    float vals[4];
    float s = 0.f, s2 = 0.f;
#pragma unroll
    for (int i = 0; i < 4; i++) {
        float v = xr[tid + i * 128];
        vals[i] = v; s += v; s2 += v * v;
    }
#pragma unroll
    for (int o = 16; o; o >>= 1) {
        s  += __shfl_down_sync(0xffffffffu, s,  o);
        s2 += __shfl_down_sync(0xffffffffu, s2, o);
    }
    __shared__ float rs[4], rs2[4];
    int wid = tid >> 5, lane = tid & 31;
    if (lane == 0) { rs[wid] = s; rs2[wid] = s2; }
    __syncthreads();
    if (tid == 0) {
        float a = 0.f, a2 = 0.f;
#pragma unroll
        for (int w = 0; w < 4; w++) { a += rs[w]; a2 += rs2[w]; }
        rs[0] = a; rs2[0] = a2;
    }
    __syncthreads();
    float mean = rs[0] * (1.0f / DM);
    float var  = rs2[0] * (1.0f / DM) - mean * mean;
    float inv  = rsqrtf(var + 1e-5f);
#pragma unroll
    for (int i = 0; i < 4; i++) {
        int c = tid + i * 128;
        orow[c] = (vals[i] - mean) * inv * g[c] + b[c];
    }
}

// ---------------- launch -------------------------------------------------------
extern "C" void kernel_launch(void* const* d_in, const int* in_sizes, int n_in,
                              void* d_out, int out_size)
{
    const float* tgt    = (const float*)d_in[0];
    const float* memory = (const float*)d_in[1];

    const size_t OW = (size_t)LAYER * DM * DM;
    const size_t OB = (size_t)LAYER * DM;
    const float* sa_wq = (const float*)d_in[4]  + OW;
    const float* sa_wk = (const float*)d_in[5]  + OW;
    const float* sa_wv = (const float*)d_in[6]  + OW;
    const float* sa_wo = (const float*)d_in[7]  + OW;
    const float* sa_bq = (const float*)d_in[8]  + OB;
    const float* sa_bk = (const float*)d_in[9]  + OB;
    const float* sa_bv = (const float*)d_in[10] + OB;
    const float* sa_bo = (const float*)d_in[11] + OB;
    const float* ca_wq = (const float*)d_in[12] + OW;
    const float* ca_wk = (const float*)d_in[13] + OW;
    const float* ca_wv = (const float*)d_in[14] + OW;
    const float* ca_wo = (const float*)d_in[15] + OW;
    const float* ca_bq = (const float*)d_in[16] + OB;
    const float* ca_bk = (const float*)d_in[17] + OB;
    const float* ca_bv = (const float*)d_in[18] + OB;
    const float* ca_bo = (const float*)d_in[19] + OB;
    const float* ff_w1 = (const float*)d_in[20] + (size_t)LAYER * DM * FFD;
    const float* ff_b1 = (const float*)d_in[21] + (size_t)LAYER * FFD;
    const float* ff_w2 = (const float*)d_in[22] + (size_t)LAYER * FFD * DM;
    const float* ff_b2 = (const float*)d_in[23] + OB;
    const float* ln_g  = (const float*)d_in[24];
    const float* ln_b  = (const float*)d_in[25];

    float *n_, *q_, *k_, *v_, *vt_, *at_, *x_, *ff_, *wt_, *w1t_, *w2t_;
    cudaGetSymbolAddress((void**)&n_,   g_n);
    cudaGetSymbolAddress((void**)&q_,   g_q);
    cudaGetSymbolAddress((void**)&k_,   g_k);
    cudaGetSymbolAddress((void**)&v_,   g_v);
    cudaGetSymbolAddress((void**)&vt_,  g_vt);
    cudaGetSymbolAddress((void**)&at_,  g_at);
    cudaGetSymbolAddress((void**)&x_,   g_x);
    cudaGetSymbolAddress((void**)&ff_,  g_ff);
    cudaGetSymbolAddress((void**)&wt_,  g_wt);
    cudaGetSymbolAddress((void**)&w1t_, g_w1t);
    cudaGetSymbolAddress((void**)&w2t_, g_w2t);

    const int S128 = 2 * (128 * 32 + 128 * 32) * 4;   // 65536
    const int SFL  = 32768 * 4;                       // 131072
    cudaFuncSetAttribute(mma_gemm<128,0>, cudaFuncAttributeMaxDynamicSharedMemorySize, S128);
    cudaFuncSetAttribute(mma_gemm<128,1>, cudaFuncAttributeMaxDynamicSharedMemorySize, S128);
    cudaFuncSetAttribute(mma_gemm<128,2>, cudaFuncAttributeMaxDynamicSharedMemorySize, S128);
    cudaFuncSetAttribute(flash_attn<1>,   cudaFuncAttributeMaxDynamicSharedMemorySize, SFL);
    cudaFuncSetAttribute(flash_attn<0>,   cudaFuncAttributeMaxDynamicSharedMemorySize, SFL);

    const int M = BB * TT;                          // 4096

    float* wqT = wt_ + 0 * DM * DM;
    float* wkT = wt_ + 1 * DM * DM;
    float* wvT = wt_ + 2 * DM * DM;
    float* woT = wt_ + 3 * DM * DM;
    float* cqT = wt_ + 4 * DM * DM;
    float* ckT = wt_ + 5 * DM * DM;
    float* cvT = wt_ + 6 * DM * DM;
    float* coT = wt_ + 7 * DM * DM;

    TP8 tp;
    tp.s[0]=sa_wq; tp.d[0]=wqT;  tp.s[1]=sa_wk; tp.d[1]=wkT;
    tp.s[2]=sa_wv; tp.d[2]=wvT;  tp.s[3]=sa_wo; tp.d[3]=woT;
    tp.s[4]=ca_wq; tp.d[4]=cqT;  tp.s[5]=ca_wk; tp.d[5]=ckT;
    tp.s[6]=ca_wv; tp.d[6]=cvT;  tp.s[7]=ca_wo; tp.d[7]=coT;
    transpose8<<<dim3(16,16,8), dim3(32,8)>>>(tp);
    transpose_one<<<dim3(FFD/32, DM/32),  dim3(32,8)>>>(ff_w1, w1t_, DM,  FFD);
    transpose_one<<<dim3(DM/32,  FFD/32), dim3(32,8)>>>(ff_w2, w2t_, FFD, DM);

    // ---- self-attention: x = tgt + SA(LN(tgt)) ----
    ln_kernel<<<M, 128>>>(tgt, ln_g, ln_b, n_);
    mma_gemm<128,0><<<dim3(4,32),256,S128>>>(n_,DM, wqT,DM, sa_bq,nullptr, q_,DM, DM);
    mma_gemm<128,0><<<dim3(4,32),256,S128>>>(n_,DM, wkT,DM, sa_bk,nullptr, k_,DM, DM);
    mma_gemm<128,0><<<dim3(4,32),256,S128>>>(n_,DM, wvT,DM, sa_bv,nullptr, v_,DM, DM);
    transpose_one<<<dim3(DM/32, M/32), dim3(32,8)>>>(v_, vt_, M, DM);
    flash_attn<1><<<dim3(4,64),256,SFL>>>(q_, k_, vt_, at_, TT);
    mma_gemm<128,2><<<dim3(4,32),256,S128>>>(at_,DM, woT,DM, sa_bo,tgt, x_,DM, DM);

    // ---- cross-attention: x += CA(LN(x), memory) ----
    ln_kernel<<<M, 128>>>(x_, ln_g, ln_b, n_);
    mma_gemm<128,0><<<dim3(4,32),256,S128>>>(n_,DM, cqT,DM, ca_bq,nullptr, q_,DM, DM);
    mma_gemm<128,0><<<dim3(4,64),256,S128>>>(memory,DM, ckT,DM, ca_bk,nullptr, k_,DM, DM);
    mma_gemm<128,0><<<dim3(4,64),256,S128>>>(memory,DM, cvT,DM, ca_bv,nullptr, v_,DM, DM);
    transpose_one<<<dim3(DM/32, (BB*SS)/32), dim3(32,8)>>>(v_, vt_, BB*SS, DM);
    flash_attn<0><<<dim3(4,64),256,SFL>>>(q_, k_, vt_, at_, SS);
    mma_gemm<128,2><<<dim3(4,32),256,S128>>>(at_,DM, coT,DM, ca_bo,x_, x_,DM, DM);

    // ---- FFN: x += W2 relu(W1 LN(x)) ----
    ln_kernel<<<M, 128>>>(x_, ln_g, ln_b, n_);
    mma_gemm<128,1><<<dim3(16,32),256,S128>>>(n_,DM,  w1t_,DM,  ff_b1,nullptr, ff_,FFD, DM);
    mma_gemm<128,2><<<dim3(4,32),256,S128>>>(ff_,FFD, w2t_,FFD, ff_b2,x_,      x_,DM,  FFD);

    // ---- final LN -> out ----
    ln_kernel<<<M, 128>>>(x_, ln_g, ln_b, (float*)d_out);
}